// round 15
// baseline (speedup 1.0000x reference)
#include <cuda_runtime.h>
#include <cuda_bf16.h>
#include <stdint.h>

#define LATENT 64
#define HID 32
#define EDIM 4
#define NMAX 100000
#define TE 128

__device__ float g_P1[NMAX*HID];
__device__ float g_PD[NMAX*EDIM];
__device__ int g_flag;

__device__ __forceinline__ uint32_t smem_u32(const void* p){
    uint32_t a; asm("{ .reg .u64 t; cvta.to.shared.u64 t, %1; cvt.u32.u64 %0, t; }":"=r"(a):"l"(p)); return a;
}
#define CVT_BF16X2(res,a,b) asm("cvt.rn.satfinite.bf16x2.f32 %0, %1, %2;":"=r"(res):"f"(b),"f"(a))
#define SW128(o) ((o)^(((o)>>3)&0x70))

__device__ __forceinline__ void ldsm4(uint32_t* r, uint32_t a){
    asm volatile("ldmatrix.sync.aligned.m8n8.x4.shared.b16 {%0,%1,%2,%3},[%4];"
        :"=r"(r[0]),"=r"(r[1]),"=r"(r[2]),"=r"(r[3]):"r"(a));
}
__device__ __forceinline__ void ldsm2(uint32_t& b0, uint32_t& b1, uint32_t a){
    asm volatile("ldmatrix.sync.aligned.m8n8.x2.shared.b16 {%0,%1},[%2];"
        :"=r"(b0),"=r"(b1):"r"(a));
}
__device__ __forceinline__ void mma16816(float* c, const uint32_t* a, uint32_t b0, uint32_t b1){
    asm volatile("mma.sync.aligned.m16n8k16.row.col.f32.bf16.bf16.f32 "
        "{%0,%1,%2,%3},{%4,%5,%6,%7},{%8,%9},{%0,%1,%2,%3};"
        :"+f"(c[0]),"+f"(c[1]),"+f"(c[2]),"+f"(c[3])
        :"r"(a[0]),"r"(a[1]),"r"(a[2]),"r"(a[3]),"r"(b0),"r"(b1));
}
__device__ __forceinline__ float bflo(uint32_t v){ return __uint_as_float(v<<16); }
__device__ __forceinline__ float bfhi(uint32_t v){ return __uint_as_float(v&0xFFFF0000u); }

__global__ void reset_flag_kernel(){ g_flag=0; }
__global__ __launch_bounds__(256) void probe_kernel(const long long* __restrict__ e,int n_probe,int n_nodes){
    int i=blockIdx.x*256+threadIdx.x; bool bad=false;
    if(i<n_probe){ long long v=__ldg(&e[i]); bad=(v<0||v>=(long long)n_nodes); }
    unsigned m=__ballot_sync(0xFFFFFFFFu,bad);
    if(m&&(threadIdx.x&31)==0) atomicOr(&g_flag,1);
}

// persistent: stage weights once per CTA, loop nodes
__global__ __launch_bounds__(256) void node_pre_kernel(
    const float* __restrict__ x,const float* __restrict__ W1,const float* __restrict__ Wdir,int n_nodes)
{
    __shared__ float sWs1[LATENT][HID];
    __shared__ float sWsD[LATENT][EDIM];
    int t=threadIdx.x;
    for(int i=t;i<LATENT*HID;i+=256){ int j=i>>5,k=i&31; sWs1[j][k]=0.5f*(W1[j*HID+k]+W1[(j+LATENT)*HID+k]); }
    for(int i=t;i<LATENT*EDIM;i+=256){ int j=i>>2,c=i&3; sWsD[j][c]=0.5f*(Wdir[j*EDIM+c]+Wdir[(j+LATENT)*EDIM+c]); }
    __syncthreads();
    int warp=t>>5,lane=t&31;
    for(int nb=blockIdx.x*8; nb<n_nodes; nb+=gridDim.x*8){
        int node=nb+warp;
        if(node>=n_nodes) continue;
        const float4* xr=(const float4*)(x+(size_t)node*LATENT);
        float a0=0.f,a1=0.f,d0=0.f,d1=0.f;
        #pragma unroll
        for(int i=0;i<16;i+=2){
            float4 v0=xr[i],v1=xr[i+1]; int j=i*4;
            a0=fmaf(v0.x,sWs1[j][lane],a0); a0=fmaf(v0.y,sWs1[j+1][lane],a0);
            a0=fmaf(v0.z,sWs1[j+2][lane],a0); a0=fmaf(v0.w,sWs1[j+3][lane],a0);
            a1=fmaf(v1.x,sWs1[j+4][lane],a1); a1=fmaf(v1.y,sWs1[j+5][lane],a1);
            a1=fmaf(v1.z,sWs1[j+6][lane],a1); a1=fmaf(v1.w,sWs1[j+7][lane],a1);
            if(lane<EDIM){
                d0=fmaf(v0.x,sWsD[j][lane],d0); d0=fmaf(v0.y,sWsD[j+1][lane],d0);
                d0=fmaf(v0.z,sWsD[j+2][lane],d0); d0=fmaf(v0.w,sWsD[j+3][lane],d0);
                d1=fmaf(v1.x,sWsD[j+4][lane],d1); d1=fmaf(v1.y,sWsD[j+5][lane],d1);
                d1=fmaf(v1.z,sWsD[j+6][lane],d1); d1=fmaf(v1.w,sWsD[j+7][lane],d1);
            }
        }
        g_P1[(size_t)node*HID+lane]=a0+a1;
        if(lane<EDIM) g_PD[(size_t)node*EDIM+lane]=d0+d1;
    }
}

// SMEM byte offsets (no BASE/BD -> 50.2 KB -> 4 CTAs/SM)
#define SM_SRC 0
#define SM_TGT 512
#define SM_W3 1024
#define SM_B1V 1536
#define SM_B2V 1664
#define SM_BOV 1792
#define SM_AHI 2048
#define SM_ALO 18432
#define SM_B1HI 34816
#define SM_B1LO 39936
#define SM_W2HI 45056
#define SM_W2LO 47616
#define SM_TOTAL 50176

__global__ __launch_bounds__(256,4) void edge_kernel(
    const float* __restrict__ x, const void* __restrict__ eidx,
    const float* __restrict__ Wdir, const float* __restrict__ bdir,
    const float* __restrict__ W1, const float* __restrict__ b1,
    const float* __restrict__ W2, const float* __restrict__ b2,
    const float* __restrict__ W3, const float* __restrict__ b3,
    float* __restrict__ out, int n_edges, int n_nodes, int ntiles)
{
    extern __shared__ char smc[];
    uint32_t sb=smem_u32(smc);
    int t=threadIdx.x;

    // ---- stage weights ONCE ----
    for(int idx=t;idx<40*64;idx+=256){
        int n=idx>>6,j=idx&63;
        float v=0.f;
        if(n<32) v=0.5f*(W1[(j+64)*32+n]-W1[j*32+n]);
        else if(n<36) v=0.5f*(Wdir[(j+64)*4+(n-32)]-Wdir[j*4+(n-32)]);
        __nv_bfloat16 h=__float2bfloat16(v);
        __nv_bfloat16 l=__float2bfloat16(v-__bfloat162float(h));
        uint32_t sw=SW128((uint32_t)(n*128+j*2));
        *(__nv_bfloat16*)(smc+SM_B1HI+sw)=h;
        *(__nv_bfloat16*)(smc+SM_B1LO+sw)=l;
    }
    for(int idx=t;idx<1024;idx+=256){
        int n=idx>>5,k=idx&31;
        float v=W2[k*32+n];
        __nv_bfloat16 h=__float2bfloat16(v);
        __nv_bfloat16 l=__float2bfloat16(v-__bfloat162float(h));
        *(__nv_bfloat16*)(smc+SM_W2HI+n*80+k*2)=h;
        *(__nv_bfloat16*)(smc+SM_W2LO+n*80+k*2)=l;
    }
    if(t<128) ((float*)(smc+SM_W3))[t]=W3[t];
    if(t<32){ ((float*)(smc+SM_B1V))[t]=b1[t]; ((float*)(smc+SM_B2V))[t]=b2[t]; }
    if(t<4) ((float*)(smc+SM_BOV))[t]=b3[t]+bdir[t];

    int lane=t&31, warp=t>>5;
    int g=lane>>2, i=lane&3;
    int we0=warp*16;

    for(int tile=blockIdx.x; tile<ntiles; tile+=gridDim.x){
        int e0=tile*TE;
        if(t<TE){
            int eg=e0+t; if(eg>=n_edges) eg=n_edges-1;
            int s_,d_;
            if(g_flag==0){ s_=(int)__ldg(&((const long long*)eidx)[eg]); d_=(int)__ldg(&((const long long*)eidx)[(size_t)n_edges+eg]); }
            else { s_=__ldg(&((const int*)eidx)[eg]); d_=__ldg(&((const int*)eidx)[(size_t)n_edges+eg]); }
            ((int*)(smc+SM_SRC))[t]=min(max(s_,0),n_nodes-1);
            ((int*)(smc+SM_TGT))[t]=min(max(d_,0),n_nodes-1);
        }
        __syncthreads();   // indices visible; prior tile done reading A tiles

        {   // gather x -> |diff| bf16 hi/lo A tiles (SW128)
            int c=t&15, el=t>>4;
            #pragma unroll
            for(int p=0;p<8;p++){
                int e=el+16*p;
                int s_=((int*)(smc+SM_SRC))[e], d_=((int*)(smc+SM_TGT))[e];
                float4 a=*(const float4*)(x+(size_t)s_*64+c*4);
                float4 b=*(const float4*)(x+(size_t)d_*64+c*4);
                float f0=fabsf(a.x-b.x),f1=fabsf(a.y-b.y),f2=fabsf(a.z-b.z),f3=fabsf(a.w-b.w);
                uint32_t h01,h23,l01,l23;
                CVT_BF16X2(h01,f0,f1); CVT_BF16X2(h23,f2,f3);
                float r0=f0-bflo(h01), r1=f1-bfhi(h01);
                float r2=f2-bflo(h23), r3=f3-bfhi(h23);
                CVT_BF16X2(l01,r0,r1); CVT_BF16X2(l23,r2,r3);
                uint32_t sw=SW128((uint32_t)(e*128+c*8));
                *(uint2*)(smc+SM_AHI+sw)=make_uint2(h01,h23);
                *(uint2*)(smc+SM_ALO+sw)=make_uint2(l01,l23);
            }
        }

        // acc init: base (P1 sums) + b1 loaded directly at fragment positions
        int r0=we0+g, r8=r0+8;
        int s0=((int*)(smc+SM_SRC))[r0], t0=((int*)(smc+SM_TGT))[r0];
        int s8=((int*)(smc+SM_SRC))[r8], t8=((int*)(smc+SM_TGT))[r8];
        float acc[5][4];
        const float* b1P=(const float*)(smc+SM_B1V);
        #pragma unroll
        for(int nb=0;nb<4;nb++){
            int col=nb*8+2*i;
            float2 bb=*(const float2*)(b1P+col);
            float2 pa=*(const float2*)(g_P1+(size_t)s0*32+col);
            float2 pb=*(const float2*)(g_P1+(size_t)t0*32+col);
            float2 pc=*(const float2*)(g_P1+(size_t)s8*32+col);
            float2 pd=*(const float2*)(g_P1+(size_t)t8*32+col);
            acc[nb][0]=pa.x+pb.x+bb.x; acc[nb][1]=pa.y+pb.y+bb.y;
            acc[nb][2]=pc.x+pd.x+bb.x; acc[nb][3]=pc.y+pd.y+bb.y;
        }
        acc[4][0]=0;acc[4][1]=0;acc[4][2]=0;acc[4][3]=0;
        __syncthreads();   // A tiles complete before ldsm

        // ---- GEMM1 (hoisted frags) ----
        #pragma unroll
        for(int kb=0;kb<4;kb++){
            uint32_t ah[4],al[4];
            {
                int row=we0+(lane&15);
                uint32_t koff=((uint32_t)kb*32+((lane>>4)&1)*16)^(((uint32_t)(row&7))*16);
                ldsm4(ah,sb+SM_AHI+(uint32_t)row*128+koff);
                ldsm4(al,sb+SM_ALO+(uint32_t)row*128+koff);
            }
            #pragma unroll
            for(int nb=0;nb<5;nb++){
                int rowb=nb*8+(lane&7);
                uint32_t offb=(uint32_t)rowb*128+(((uint32_t)kb*32+((lane>>3)&1)*16)^(((uint32_t)(rowb&7))*16));
                uint32_t bh0,bh1,bl0,bl1;
                ldsm2(bh0,bh1,sb+SM_B1HI+offb);
                ldsm2(bl0,bl1,sb+SM_B1LO+offb);
                mma16816(acc[nb],ah,bh0,bh1);
                mma16816(acc[nb],ah,bl0,bl1);
                mma16816(acc[nb],al,bh0,bh1);
            }
        }

        // epilogue1: relu; convert to bf16 hi/lo A2 frags (h1 reconstructed later)
        uint32_t a2h[2][4], a2l[2][4];
        #pragma unroll
        for(int kb2=0;kb2<2;kb2++){
            #pragma unroll
            for(int q=0;q<4;q++){
                int nb=2*kb2+(q>>1);
                int c0=(q&1)*2;
                float v0=fmaxf(acc[nb][c0],0.f), v1=fmaxf(acc[nb][c0+1],0.f);
                uint32_t h; CVT_BF16X2(h,v0,v1);
                float r0v=v0-bflo(h), r1v=v1-bfhi(h);
                uint32_t l; CVT_BF16X2(l,r0v,r1v);
                int ridx=(q>>1)*2+(q&1);
                a2h[kb2][ridx]=h; a2l[kb2][ridx]=l;
            }
        }

        // ---- GEMM2 (hoisted W frags) ----
        float acc2[4][4];
        #pragma unroll
        for(int nb=0;nb<4;nb++){ acc2[nb][0]=0;acc2[nb][1]=0;acc2[nb][2]=0;acc2[nb][3]=0; }
        #pragma unroll
        for(int kb2=0;kb2<2;kb2++){
            #pragma unroll
            for(int nb=0;nb<4;nb++){
                int rowb=nb*8+(lane&7);
                uint32_t base2=(uint32_t)rowb*80+(uint32_t)kb2*32+((lane>>3)&1)*16;
                uint32_t wh0,wh1,wl0,wl1;
                ldsm2(wh0,wh1,sb+SM_W2HI+base2);
                ldsm2(wl0,wl1,sb+SM_W2LO+base2);
                mma16816(acc2[nb],a2h[kb2],wh0,wh1);
                mma16816(acc2[nb],a2h[kb2],wl0,wl1);
                mma16816(acc2[nb],a2l[kb2],wh0,wh1);
            }
        }

        // epilogue2: h2 = relu(acc2 + h1 + b2); project W3; add dir; reduce; store
        const float* b2P=(const float*)(smc+SM_B2V);
        const float* w3P=(const float*)(smc+SM_W3);
        {
            float pg[4]={0,0,0,0}, ph[4]={0,0,0,0};
            #pragma unroll
            for(int nb=0;nb<4;nb++){
                int col=nb*8+2*i;
                int kb2=nb>>1;
                int rA=(nb&1)*2, rB=rA+1;
                float h1_0=bflo(a2h[kb2][rA])+bflo(a2l[kb2][rA]);
                float h1_1=bfhi(a2h[kb2][rA])+bfhi(a2l[kb2][rA]);
                float h1_2=bflo(a2h[kb2][rB])+bflo(a2l[kb2][rB]);
                float h1_3=bfhi(a2h[kb2][rB])+bfhi(a2l[kb2][rB]);
                float2 bb=*(const float2*)(b2P+col);
                float h0=fmaxf(acc2[nb][0]+h1_0+bb.x,0.f);
                float h1v=fmaxf(acc2[nb][1]+h1_1+bb.y,0.f);
                float h2v=fmaxf(acc2[nb][2]+h1_2+bb.x,0.f);
                float h3v=fmaxf(acc2[nb][3]+h1_3+bb.y,0.f);
                float4 wa=*(const float4*)(w3P+col*4);
                float4 wb=*(const float4*)(w3P+(col+1)*4);
                pg[0]=fmaf(h0,wa.x,fmaf(h1v,wb.x,pg[0]));
                pg[1]=fmaf(h0,wa.y,fmaf(h1v,wb.y,pg[1]));
                pg[2]=fmaf(h0,wa.z,fmaf(h1v,wb.z,pg[2]));
                pg[3]=fmaf(h0,wa.w,fmaf(h1v,wb.w,pg[3]));
                ph[0]=fmaf(h2v,wa.x,fmaf(h3v,wb.x,ph[0]));
                ph[1]=fmaf(h2v,wa.y,fmaf(h3v,wb.y,ph[1]));
                ph[2]=fmaf(h2v,wa.z,fmaf(h3v,wb.z,ph[2]));
                ph[3]=fmaf(h2v,wa.w,fmaf(h3v,wb.w,ph[3]));
            }
            pg[2*i]  +=acc[4][0];
            pg[2*i+1]+=acc[4][1];
            ph[2*i]  +=acc[4][2];
            ph[2*i+1]+=acc[4][3];
            #pragma unroll
            for(int c=0;c<4;c++){
                pg[c]+=__shfl_xor_sync(0xFFFFFFFFu,pg[c],1);
                pg[c]+=__shfl_xor_sync(0xFFFFFFFFu,pg[c],2);
                ph[c]+=__shfl_xor_sync(0xFFFFFFFFu,ph[c],1);
                ph[c]+=__shfl_xor_sync(0xFFFFFFFFu,ph[c],2);
            }
            if(i==0){
                float4 bo=*(const float4*)(smc+SM_BOV);
                float4 pd0a=*(const float4*)(g_PD+(size_t)s0*4);
                float4 pd0b=*(const float4*)(g_PD+(size_t)t0*4);
                float4 pd8a=*(const float4*)(g_PD+(size_t)s8*4);
                float4 pd8b=*(const float4*)(g_PD+(size_t)t8*4);
                int eg0=e0+r0, eg8=e0+r8;
                if(eg0<n_edges)
                    *(float4*)(out+(size_t)eg0*4)=make_float4(
                        pg[0]+pd0a.x+pd0b.x+bo.x, pg[1]+pd0a.y+pd0b.y+bo.y,
                        pg[2]+pd0a.z+pd0b.z+bo.z, pg[3]+pd0a.w+pd0b.w+bo.w);
                if(eg8<n_edges)
                    *(float4*)(out+(size_t)eg8*4)=make_float4(
                        ph[0]+pd8a.x+pd8b.x+bo.x, ph[1]+pd8a.y+pd8b.y+bo.y,
                        ph[2]+pd8a.z+pd8b.z+bo.z, ph[3]+pd8a.w+pd8b.w+bo.w);
            }
        }
    }
}

extern "C" void kernel_launch(void* const* d_in, const int* in_sizes, int n_in,
                              void* d_out, int out_size)
{
    const float* x=(const float*)d_in[0];
    const void* eidx=d_in[1];
    const float* Wdir=(const float*)d_in[2];
    const float* bdir=(const float*)d_in[3];
    const float* W1=(const float*)d_in[4];
    const float* b1=(const float*)d_in[5];
    const float* W2=(const float*)d_in[6];
    const float* b2=(const float*)d_in[7];
    const float* W3=(const float*)d_in[8];
    const float* b3=(const float*)d_in[9];
    float* out=(float*)d_out;

    int n_nodes=in_sizes[0]/LATENT;
    int n_edges=in_sizes[1]/2;

    int n_probe=n_edges<32768?n_edges:32768;
    reset_flag_kernel<<<1,1>>>();
    probe_kernel<<<(n_probe+255)/256,256>>>((const long long*)eidx,n_probe,n_nodes);
    int npb=(n_nodes+7)/8; if(npb>444) npb=444;
    node_pre_kernel<<<npb,256>>>(x,W1,Wdir,n_nodes);

    cudaFuncSetAttribute(edge_kernel,cudaFuncAttributeMaxDynamicSharedMemorySize,SM_TOTAL);
    int ntiles=(n_edges+TE-1)/TE;
    int nblk=592; if(ntiles<nblk) nblk=ntiles;   // 4 CTAs/SM x 148
    edge_kernel<<<nblk,256,SM_TOTAL>>>(x,eidx,Wdir,bdir,W1,b1,W2,b2,W3,b3,out,n_edges,n_nodes,ntiles);
}

// round 16
// speedup vs baseline: 1.1382x; 1.1382x over previous
#include <cuda_runtime.h>
#include <cuda_bf16.h>
#include <stdint.h>

#define LATENT 64
#define HID 32
#define EDIM 4
#define NMAX 100000
#define TE 128

__device__ float g_P1[NMAX*HID];
__device__ float g_PD[NMAX*EDIM];
__device__ int g_flag = 0;   // 0 => int64 edge_index; probe ORs 1 if int32

__device__ __forceinline__ uint32_t smem_u32(const void* p){
    uint32_t a; asm("{ .reg .u64 t; cvta.to.shared.u64 t, %1; cvt.u32.u64 %0, t; }":"=r"(a):"l"(p)); return a;
}
#define CVT_BF16X2(res,a,b) asm("cvt.rn.satfinite.bf16x2.f32 %0, %1, %2;":"=r"(res):"f"(b),"f"(a))
#define SW128(o) ((o)^(((o)>>3)&0x70))

__device__ __forceinline__ void ldsm4(uint32_t* r, uint32_t a){
    asm volatile("ldmatrix.sync.aligned.m8n8.x4.shared.b16 {%0,%1,%2,%3},[%4];"
        :"=r"(r[0]),"=r"(r[1]),"=r"(r[2]),"=r"(r[3]):"r"(a));
}
__device__ __forceinline__ void ldsm2(uint32_t& b0, uint32_t& b1, uint32_t a){
    asm volatile("ldmatrix.sync.aligned.m8n8.x2.shared.b16 {%0,%1},[%2];"
        :"=r"(b0),"=r"(b1):"r"(a));
}
__device__ __forceinline__ void mma16816(float* c, const uint32_t* a, uint32_t b0, uint32_t b1){
    asm volatile("mma.sync.aligned.m16n8k16.row.col.f32.bf16.bf16.f32 "
        "{%0,%1,%2,%3},{%4,%5,%6,%7},{%8,%9},{%0,%1,%2,%3};"
        :"+f"(c[0]),"+f"(c[1]),"+f"(c[2]),"+f"(c[3])
        :"r"(a[0]),"r"(a[1]),"r"(a[2]),"r"(a[3]),"r"(b0),"r"(b1));
}

__global__ __launch_bounds__(256) void probe_kernel(const long long* __restrict__ e,int n_probe,int n_nodes){
    int i=blockIdx.x*256+threadIdx.x; bool bad=false;
    if(i<n_probe){ long long v=__ldg(&e[i]); bad=(v<0||v>=(long long)n_nodes); }
    unsigned m=__ballot_sync(0xFFFFFFFFu,bad);
    if(m&&(threadIdx.x&31)==0) atomicOr(&g_flag,1);
}

// persistent: stage weights once per CTA, grid-stride over nodes
__global__ __launch_bounds__(256) void node_pre_kernel(
    const float* __restrict__ x,const float* __restrict__ W1,const float* __restrict__ Wdir,int n_nodes)
{
    __shared__ float sWs1[LATENT][HID];
    __shared__ float sWsD[LATENT][EDIM];
    int t=threadIdx.x;
    for(int i=t;i<LATENT*HID;i+=256){ int j=i>>5,k=i&31; sWs1[j][k]=0.5f*(W1[j*HID+k]+W1[(j+LATENT)*HID+k]); }
    for(int i=t;i<LATENT*EDIM;i+=256){ int j=i>>2,c=i&3; sWsD[j][c]=0.5f*(Wdir[j*EDIM+c]+Wdir[(j+LATENT)*EDIM+c]); }
    __syncthreads();
    int warp=t>>5,lane=t&31;
    for(int nb=blockIdx.x*8; nb<n_nodes; nb+=gridDim.x*8){
        int node=nb+warp;
        if(node>=n_nodes) continue;
        const float4* xr=(const float4*)(x+(size_t)node*LATENT);
        float a0=0.f,a1=0.f,d0=0.f,d1=0.f;
        #pragma unroll
        for(int i=0;i<16;i+=2){
            float4 v0=xr[i],v1=xr[i+1]; int j=i*4;
            a0=fmaf(v0.x,sWs1[j][lane],a0); a0=fmaf(v0.y,sWs1[j+1][lane],a0);
            a0=fmaf(v0.z,sWs1[j+2][lane],a0); a0=fmaf(v0.w,sWs1[j+3][lane],a0);
            a1=fmaf(v1.x,sWs1[j+4][lane],a1); a1=fmaf(v1.y,sWs1[j+5][lane],a1);
            a1=fmaf(v1.z,sWs1[j+6][lane],a1); a1=fmaf(v1.w,sWs1[j+7][lane],a1);
            if(lane<EDIM){
                d0=fmaf(v0.x,sWsD[j][lane],d0); d0=fmaf(v0.y,sWsD[j+1][lane],d0);
                d0=fmaf(v0.z,sWsD[j+2][lane],d0); d0=fmaf(v0.w,sWsD[j+3][lane],d0);
                d1=fmaf(v1.x,sWsD[j+4][lane],d1); d1=fmaf(v1.y,sWsD[j+5][lane],d1);
                d1=fmaf(v1.z,sWsD[j+6][lane],d1); d1=fmaf(v1.w,sWsD[j+7][lane],d1);
            }
        }
        g_P1[(size_t)node*HID+lane]=a0+a1;
        if(lane<EDIM) g_PD[(size_t)node*EDIM+lane]=d0+d1;
    }
}

// SMEM byte offsets (R14 layout, 70.7 KB -> 3 CTAs/SM)
#define SM_SRC 0
#define SM_TGT 512
#define SM_W3 1024
#define SM_B1V 1536
#define SM_B2V 1664
#define SM_BOV 1792
#define SM_AHI 2048
#define SM_ALO 18432
#define SM_B1HI 34816
#define SM_B1LO 39936
#define SM_W2HI 45056
#define SM_W2LO 47616
#define SM_BASE 50176
#define SM_BD 68608
#define SM_TOTAL 70656

__global__ __launch_bounds__(256,3) void edge_kernel(
    const float* __restrict__ x, const void* __restrict__ eidx,
    const float* __restrict__ Wdir, const float* __restrict__ bdir,
    const float* __restrict__ W1, const float* __restrict__ b1,
    const float* __restrict__ W2, const float* __restrict__ b2,
    const float* __restrict__ W3, const float* __restrict__ b3,
    float* __restrict__ out, int n_edges, int n_nodes, int ntiles)
{
    extern __shared__ char smc[];
    uint32_t sb=smem_u32(smc);
    int t=threadIdx.x;

    // ---- stage weights ONCE (persistent CTA) ----
    for(int idx=t;idx<40*64;idx+=256){
        int n=idx>>6,j=idx&63;
        float v=0.f;
        if(n<32) v=0.5f*(W1[(j+64)*32+n]-W1[j*32+n]);
        else if(n<36) v=0.5f*(Wdir[(j+64)*4+(n-32)]-Wdir[j*4+(n-32)]);
        __nv_bfloat16 h=__float2bfloat16(v);
        __nv_bfloat16 l=__float2bfloat16(v-__bfloat162float(h));
        uint32_t sw=SW128((uint32_t)(n*128+j*2));
        *(__nv_bfloat16*)(smc+SM_B1HI+sw)=h;
        *(__nv_bfloat16*)(smc+SM_B1LO+sw)=l;
    }
    for(int idx=t;idx<1024;idx+=256){
        int n=idx>>5,k=idx&31;
        float v=W2[k*32+n];
        __nv_bfloat16 h=__float2bfloat16(v);
        __nv_bfloat16 l=__float2bfloat16(v-__bfloat162float(h));
        *(__nv_bfloat16*)(smc+SM_W2HI+n*80+k*2)=h;
        *(__nv_bfloat16*)(smc+SM_W2LO+n*80+k*2)=l;
    }
    if(t<128) ((float*)(smc+SM_W3))[t]=W3[t];
    if(t<32){ ((float*)(smc+SM_B1V))[t]=b1[t]; ((float*)(smc+SM_B2V))[t]=b2[t]; }
    if(t<4) ((float*)(smc+SM_BOV))[t]=b3[t]+bdir[t];

    int lane=t&31, warp=t>>5;
    int g=lane>>2, i=lane&3;
    int we0=warp*16;

    for(int tile=blockIdx.x; tile<ntiles; tile+=gridDim.x){
        int e0=tile*TE;
        if(t<TE){
            int eg=e0+t; if(eg>=n_edges) eg=n_edges-1;
            int s_,d_;
            if(g_flag==0){ s_=(int)__ldg(&((const long long*)eidx)[eg]); d_=(int)__ldg(&((const long long*)eidx)[(size_t)n_edges+eg]); }
            else { s_=__ldg(&((const int*)eidx)[eg]); d_=__ldg(&((const int*)eidx)[(size_t)n_edges+eg]); }
            ((int*)(smc+SM_SRC))[t]=min(max(s_,0),n_nodes-1);
            ((int*)(smc+SM_TGT))[t]=min(max(d_,0),n_nodes-1);
        }
        __syncthreads();

        {   // gather x -> |diff| bf16 hi/lo A tiles (SW128)
            int c=t&15, el=t>>4;
            #pragma unroll
            for(int p=0;p<8;p++){
                int e=el+16*p;
                int s_=((int*)(smc+SM_SRC))[e], d_=((int*)(smc+SM_TGT))[e];
                float4 a=*(const float4*)(x+(size_t)s_*64+c*4);
                float4 b=*(const float4*)(x+(size_t)d_*64+c*4);
                float f0=fabsf(a.x-b.x),f1=fabsf(a.y-b.y),f2=fabsf(a.z-b.z),f3=fabsf(a.w-b.w);
                uint32_t h01,h23,l01,l23;
                CVT_BF16X2(h01,f0,f1); CVT_BF16X2(h23,f2,f3);
                float r0=f0-__uint_as_float(h01<<16);
                float r1=f1-__uint_as_float(h01&0xFFFF0000u);
                float r2=f2-__uint_as_float(h23<<16);
                float r3=f3-__uint_as_float(h23&0xFFFF0000u);
                CVT_BF16X2(l01,r0,r1); CVT_BF16X2(l23,r2,r3);
                uint32_t sw=SW128((uint32_t)(e*128+c*8));
                *(uint2*)(smc+SM_AHI+sw)=make_uint2(h01,h23);
                *(uint2*)(smc+SM_ALO+sw)=make_uint2(l01,l23);
            }
        }
        {   // gather P1 sums -> base (fp32 stride 36) — COALESCED
            int c=t&7, el=t>>3;
            #pragma unroll
            for(int p=0;p<4;p++){
                int e=el+32*p;
                int s_=((int*)(smc+SM_SRC))[e], d_=((int*)(smc+SM_TGT))[e];
                float4 a=*(const float4*)(g_P1+(size_t)s_*32+c*4);
                float4 b=*(const float4*)(g_P1+(size_t)d_*32+c*4);
                *(float4*)(smc+SM_BASE+(e*36+c*4)*4)=make_float4(a.x+b.x,a.y+b.y,a.z+b.z,a.w+b.w);
            }
        }
        if(t<TE){   // PD sums
            int s_=((int*)(smc+SM_SRC))[t], d_=((int*)(smc+SM_TGT))[t];
            float4 a=*(const float4*)(g_PD+(size_t)s_*4);
            float4 b=*(const float4*)(g_PD+(size_t)d_*4);
            *(float4*)(smc+SM_BD+t*16)=make_float4(a.x+b.x,a.y+b.y,a.z+b.z,a.w+b.w);
        }
        __syncthreads();

        // ---- GEMM1 (hoisted frags) ----
        float acc[5][4];
        #pragma unroll
        for(int nb=0;nb<5;nb++){ acc[nb][0]=0;acc[nb][1]=0;acc[nb][2]=0;acc[nb][3]=0; }

        #pragma unroll
        for(int kb=0;kb<4;kb++){
            uint32_t ah[4],al[4];
            {
                int row=we0+(lane&15);
                uint32_t koff=((uint32_t)kb*32+((lane>>4)&1)*16)^(((uint32_t)(row&7))*16);
                ldsm4(ah,sb+SM_AHI+(uint32_t)row*128+koff);
                ldsm4(al,sb+SM_ALO+(uint32_t)row*128+koff);
            }
            #pragma unroll
            for(int nb=0;nb<5;nb++){
                int rowb=nb*8+(lane&7);
                uint32_t offb=(uint32_t)rowb*128+(((uint32_t)kb*32+((lane>>3)&1)*16)^(((uint32_t)(rowb&7))*16));
                uint32_t bh0,bh1,bl0,bl1;
                ldsm2(bh0,bh1,sb+SM_B1HI+offb);
                ldsm2(bl0,bl1,sb+SM_B1LO+offb);
                mma16816(acc[nb],ah,bh0,bh1);
                mma16816(acc[nb],ah,bl0,bl1);
                mma16816(acc[nb],al,bh0,bh1);
            }
        }

        // epilogue1: h1 = relu(acc + base + b1) cols 0..31 (in place)
        const float* baseP=(const float*)(smc+SM_BASE);
        const float* b1P=(const float*)(smc+SM_B1V);
        {
            int r0=we0+g, r8=r0+8;
            #pragma unroll
            for(int nb=0;nb<4;nb++){
                int col=nb*8+2*i;
                float2 bb=*(const float2*)(b1P+col);
                float2 q0=*(const float2*)(baseP+r0*36+col);
                float2 q8=*(const float2*)(baseP+r8*36+col);
                acc[nb][0]=fmaxf(acc[nb][0]+q0.x+bb.x,0.f);
                acc[nb][1]=fmaxf(acc[nb][1]+q0.y+bb.y,0.f);
                acc[nb][2]=fmaxf(acc[nb][2]+q8.x+bb.x,0.f);
                acc[nb][3]=fmaxf(acc[nb][3]+q8.y+bb.y,0.f);
            }
        }

        // build A2 frags (hi/lo) in registers
        uint32_t a2h[2][4], a2l[2][4];
        #pragma unroll
        for(int kb2=0;kb2<2;kb2++){
            #pragma unroll
            for(int q=0;q<4;q++){
                int nb=2*kb2+(q>>1);
                int c0=(q&1)*2;
                float v0=acc[nb][c0], v1=acc[nb][c0+1];
                uint32_t h; CVT_BF16X2(h,v0,v1);
                float r0=v0-__uint_as_float(h<<16);
                float r1=v1-__uint_as_float(h&0xFFFF0000u);
                uint32_t l; CVT_BF16X2(l,r0,r1);
                int ridx=(q>>1)*2+(q&1);
                a2h[kb2][ridx]=h; a2l[kb2][ridx]=l;
            }
        }

        // ---- GEMM2 (hoisted W frags) ----
        float acc2[4][4];
        #pragma unroll
        for(int nb=0;nb<4;nb++){ acc2[nb][0]=0;acc2[nb][1]=0;acc2[nb][2]=0;acc2[nb][3]=0; }
        #pragma unroll
        for(int kb2=0;kb2<2;kb2++){
            #pragma unroll
            for(int nb=0;nb<4;nb++){
                int rowb=nb*8+(lane&7);
                uint32_t base2=(uint32_t)rowb*80+(uint32_t)kb2*32+((lane>>3)&1)*16;
                uint32_t wh0,wh1,wl0,wl1;
                ldsm2(wh0,wh1,sb+SM_W2HI+base2);
                ldsm2(wl0,wl1,sb+SM_W2LO+base2);
                mma16816(acc2[nb],a2h[kb2],wh0,wh1);
                mma16816(acc2[nb],a2h[kb2],wl0,wl1);
                mma16816(acc2[nb],a2l[kb2],wh0,wh1);
            }
        }

        // epilogue2
        const float* b2P=(const float*)(smc+SM_B2V);
        const float* w3P=(const float*)(smc+SM_W3);
        {
            float pg[4]={0,0,0,0}, ph[4]={0,0,0,0};
            #pragma unroll
            for(int nb=0;nb<4;nb++){
                int col=nb*8+2*i;
                float2 bb=*(const float2*)(b2P+col);
                float h0=fmaxf(acc2[nb][0]+acc[nb][0]+bb.x,0.f);
                float h1v=fmaxf(acc2[nb][1]+acc[nb][1]+bb.y,0.f);
                float h2v=fmaxf(acc2[nb][2]+acc[nb][2]+bb.x,0.f);
                float h3v=fmaxf(acc2[nb][3]+acc[nb][3]+bb.y,0.f);
                float4 wa=*(const float4*)(w3P+col*4);
                float4 wb=*(const float4*)(w3P+(col+1)*4);
                pg[0]=fmaf(h0,wa.x,fmaf(h1v,wb.x,pg[0]));
                pg[1]=fmaf(h0,wa.y,fmaf(h1v,wb.y,pg[1]));
                pg[2]=fmaf(h0,wa.z,fmaf(h1v,wb.z,pg[2]));
                pg[3]=fmaf(h0,wa.w,fmaf(h1v,wb.w,pg[3]));
                ph[0]=fmaf(h2v,wa.x,fmaf(h3v,wb.x,ph[0]));
                ph[1]=fmaf(h2v,wa.y,fmaf(h3v,wb.y,ph[1]));
                ph[2]=fmaf(h2v,wa.z,fmaf(h3v,wb.z,ph[2]));
                ph[3]=fmaf(h2v,wa.w,fmaf(h3v,wb.w,ph[3]));
            }
            pg[2*i]  +=acc[4][0];
            pg[2*i+1]+=acc[4][1];
            ph[2*i]  +=acc[4][2];
            ph[2*i+1]+=acc[4][3];
            #pragma unroll
            for(int c=0;c<4;c++){
                pg[c]+=__shfl_xor_sync(0xFFFFFFFFu,pg[c],1);
                pg[c]+=__shfl_xor_sync(0xFFFFFFFFu,pg[c],2);
                ph[c]+=__shfl_xor_sync(0xFFFFFFFFu,ph[c],1);
                ph[c]+=__shfl_xor_sync(0xFFFFFFFFu,ph[c],2);
            }
            if(i==0){
                float4 bo=*(const float4*)(smc+SM_BOV);
                int el0=we0+g, el8=el0+8;
                float4 p0=*(const float4*)(smc+SM_BD+el0*16);
                float4 p8=*(const float4*)(smc+SM_BD+el8*16);
                int eg0=e0+el0, eg8=e0+el8;
                if(eg0<n_edges)
                    *(float4*)(out+(size_t)eg0*4)=make_float4(pg[0]+p0.x+bo.x,pg[1]+p0.y+bo.y,pg[2]+p0.z+bo.z,pg[3]+p0.w+bo.w);
                if(eg8<n_edges)
                    *(float4*)(out+(size_t)eg8*4)=make_float4(ph[0]+p8.x+bo.x,ph[1]+p8.y+bo.y,ph[2]+p8.z+bo.z,ph[3]+p8.w+bo.w);
            }
        }
    }
}

extern "C" void kernel_launch(void* const* d_in, const int* in_sizes, int n_in,
                              void* d_out, int out_size)
{
    const float* x=(const float*)d_in[0];
    const void* eidx=d_in[1];
    const float* Wdir=(const float*)d_in[2];
    const float* bdir=(const float*)d_in[3];
    const float* W1=(const float*)d_in[4];
    const float* b1=(const float*)d_in[5];
    const float* W2=(const float*)d_in[6];
    const float* b2=(const float*)d_in[7];
    const float* W3=(const float*)d_in[8];
    const float* b3=(const float*)d_in[9];
    float* out=(float*)d_out;

    int n_nodes=in_sizes[0]/LATENT;
    int n_edges=in_sizes[1]/2;

    int n_probe=n_edges<32768?n_edges:32768;
    probe_kernel<<<(n_probe+255)/256,256>>>((const long long*)eidx,n_probe,n_nodes);

    int npb=(n_nodes+7)/8; if(npb>1184) npb=1184;
    node_pre_kernel<<<npb,256>>>(x,W1,Wdir,n_nodes);

    cudaFuncSetAttribute(edge_kernel,cudaFuncAttributeMaxDynamicSharedMemorySize,SM_TOTAL);
    int ntiles=(n_edges+TE-1)/TE;
    int nblk=444; if(ntiles<nblk) nblk=ntiles;
    edge_kernel<<<nblk,256,SM_TOTAL>>>(x,eidx,Wdir,bdir,W1,b1,W2,b2,W3,b3,out,n_edges,n_nodes,ntiles);
}

// round 17
// speedup vs baseline: 1.1873x; 1.0431x over previous
#include <cuda_runtime.h>
#include <cuda_bf16.h>
#include <stdint.h>

#define LATENT 64
#define HID 32
#define EDIM 4
#define NMAX 100000
#define TE 128

__device__ float g_P1[NMAX*HID];
__device__ float g_PD[NMAX*EDIM];
__device__ int g_flag = 0;   // 0 => int64 edge_index; probe ORs 1 if int32

__device__ __forceinline__ uint32_t smem_u32(const void* p){
    uint32_t a; asm("{ .reg .u64 t; cvta.to.shared.u64 t, %1; cvt.u32.u64 %0, t; }":"=r"(a):"l"(p)); return a;
}
#define CVT_BF16X2(res,a,b) asm("cvt.rn.satfinite.bf16x2.f32 %0, %1, %2;":"=r"(res):"f"(b),"f"(a))
#define SW128(o) ((o)^(((o)>>3)&0x70))

__device__ __forceinline__ void ldsm4(uint32_t* r, uint32_t a){
    asm volatile("ldmatrix.sync.aligned.m8n8.x4.shared.b16 {%0,%1,%2,%3},[%4];"
        :"=r"(r[0]),"=r"(r[1]),"=r"(r[2]),"=r"(r[3]):"r"(a));
}
__device__ __forceinline__ void ldsm2(uint32_t& b0, uint32_t& b1, uint32_t a){
    asm volatile("ldmatrix.sync.aligned.m8n8.x2.shared.b16 {%0,%1},[%2];"
        :"=r"(b0),"=r"(b1):"r"(a));
}
__device__ __forceinline__ void mma16816(float* c, const uint32_t* a, uint32_t b0, uint32_t b1){
    asm volatile("mma.sync.aligned.m16n8k16.row.col.f32.bf16.bf16.f32 "
        "{%0,%1,%2,%3},{%4,%5,%6,%7},{%8,%9},{%0,%1,%2,%3};"
        :"+f"(c[0]),"+f"(c[1]),"+f"(c[2]),"+f"(c[3])
        :"r"(a[0]),"r"(a[1]),"r"(a[2]),"r"(a[3]),"r"(b0),"r"(b1));
}

__global__ __launch_bounds__(256) void probe_kernel(const long long* __restrict__ e,int n_probe,int n_nodes){
    int i=blockIdx.x*256+threadIdx.x; bool bad=false;
    if(i<n_probe){ long long v=__ldg(&e[i]); bad=(v<0||v>=(long long)n_nodes); }
    unsigned m=__ballot_sync(0xFFFFFFFFu,bad);
    if(m&&(threadIdx.x&31)==0) atomicOr(&g_flag,1);
}

// persistent; 2 nodes per warp (independent chains -> 2x MLP)
__global__ __launch_bounds__(256) void node_pre_kernel(
    const float* __restrict__ x,const float* __restrict__ W1,const float* __restrict__ Wdir,int n_nodes)
{
    __shared__ float sWs1[LATENT][HID];
    __shared__ float sWsD[LATENT][EDIM];
    int t=threadIdx.x;
    for(int i=t;i<LATENT*HID;i+=256){ int j=i>>5,k=i&31; sWs1[j][k]=0.5f*(W1[j*HID+k]+W1[(j+LATENT)*HID+k]); }
    for(int i=t;i<LATENT*EDIM;i+=256){ int j=i>>2,c=i&3; sWsD[j][c]=0.5f*(Wdir[j*EDIM+c]+Wdir[(j+LATENT)*EDIM+c]); }
    __syncthreads();
    int warp=t>>5,lane=t&31;
    for(int nb=blockIdx.x*16; nb<n_nodes; nb+=gridDim.x*16){
        int nodeA=nb+warp, nodeB=nb+8+warp;
        bool okA=nodeA<n_nodes, okB=nodeB<n_nodes;
        const float4* xa=(const float4*)(x+(size_t)(okA?nodeA:0)*LATENT);
        const float4* xb=(const float4*)(x+(size_t)(okB?nodeB:0)*LATENT);
        float aA0=0.f,aA1=0.f,dA0=0.f,dA1=0.f;
        float aB0=0.f,aB1=0.f,dB0=0.f,dB1=0.f;
        #pragma unroll
        for(int i=0;i<16;i+=2){
            float4 vA0=xa[i],vA1=xa[i+1];
            float4 vB0=xb[i],vB1=xb[i+1];
            int j=i*4;
            aA0=fmaf(vA0.x,sWs1[j][lane],aA0);   aA0=fmaf(vA0.y,sWs1[j+1][lane],aA0);
            aA0=fmaf(vA0.z,sWs1[j+2][lane],aA0); aA0=fmaf(vA0.w,sWs1[j+3][lane],aA0);
            aA1=fmaf(vA1.x,sWs1[j+4][lane],aA1); aA1=fmaf(vA1.y,sWs1[j+5][lane],aA1);
            aA1=fmaf(vA1.z,sWs1[j+6][lane],aA1); aA1=fmaf(vA1.w,sWs1[j+7][lane],aA1);
            aB0=fmaf(vB0.x,sWs1[j][lane],aB0);   aB0=fmaf(vB0.y,sWs1[j+1][lane],aB0);
            aB0=fmaf(vB0.z,sWs1[j+2][lane],aB0); aB0=fmaf(vB0.w,sWs1[j+3][lane],aB0);
            aB1=fmaf(vB1.x,sWs1[j+4][lane],aB1); aB1=fmaf(vB1.y,sWs1[j+5][lane],aB1);
            aB1=fmaf(vB1.z,sWs1[j+6][lane],aB1); aB1=fmaf(vB1.w,sWs1[j+7][lane],aB1);
            if(lane<EDIM){
                dA0=fmaf(vA0.x,sWsD[j][lane],dA0);   dA0=fmaf(vA0.y,sWsD[j+1][lane],dA0);
                dA0=fmaf(vA0.z,sWsD[j+2][lane],dA0); dA0=fmaf(vA0.w,sWsD[j+3][lane],dA0);
                dA1=fmaf(vA1.x,sWsD[j+4][lane],dA1); dA1=fmaf(vA1.y,sWsD[j+5][lane],dA1);
                dA1=fmaf(vA1.z,sWsD[j+6][lane],dA1); dA1=fmaf(vA1.w,sWsD[j+7][lane],dA1);
                dB0=fmaf(vB0.x,sWsD[j][lane],dB0);   dB0=fmaf(vB0.y,sWsD[j+1][lane],dB0);
                dB0=fmaf(vB0.z,sWsD[j+2][lane],dB0); dB0=fmaf(vB0.w,sWsD[j+3][lane],dB0);
                dB1=fmaf(vB1.x,sWsD[j+4][lane],dB1); dB1=fmaf(vB1.y,sWsD[j+5][lane],dB1);
                dB1=fmaf(vB1.z,sWsD[j+6][lane],dB1); dB1=fmaf(vB1.w,sWsD[j+7][lane],dB1);
            }
        }
        if(okA){
            g_P1[(size_t)nodeA*HID+lane]=aA0+aA1;
            if(lane<EDIM) g_PD[(size_t)nodeA*EDIM+lane]=dA0+dA1;
        }
        if(okB){
            g_P1[(size_t)nodeB*HID+lane]=aB0+aB1;
            if(lane<EDIM) g_PD[(size_t)nodeB*EDIM+lane]=dB0+dB1;
        }
    }
}

// SMEM byte offsets (R14 layout, 70.7 KB -> 3 CTAs/SM)
#define SM_SRC 0
#define SM_TGT 512
#define SM_W3 1024
#define SM_B1V 1536
#define SM_B2V 1664
#define SM_BOV 1792
#define SM_AHI 2048
#define SM_ALO 18432
#define SM_B1HI 34816
#define SM_B1LO 39936
#define SM_W2HI 45056
#define SM_W2LO 47616
#define SM_BASE 50176
#define SM_BD 68608
#define SM_TOTAL 70656

__global__ __launch_bounds__(256,3) void edge_kernel(
    const float* __restrict__ x, const void* __restrict__ eidx,
    const float* __restrict__ Wdir, const float* __restrict__ bdir,
    const float* __restrict__ W1, const float* __restrict__ b1,
    const float* __restrict__ W2, const float* __restrict__ b2,
    const float* __restrict__ W3, const float* __restrict__ b3,
    float* __restrict__ out, int n_edges, int n_nodes, int ntiles)
{
    extern __shared__ char smc[];
    uint32_t sb=smem_u32(smc);
    int t=threadIdx.x;

    // ---- stage weights ONCE (persistent CTA) ----
    for(int idx=t;idx<40*64;idx+=256){
        int n=idx>>6,j=idx&63;
        float v=0.f;
        if(n<32) v=0.5f*(W1[(j+64)*32+n]-W1[j*32+n]);
        else if(n<36) v=0.5f*(Wdir[(j+64)*4+(n-32)]-Wdir[j*4+(n-32)]);
        __nv_bfloat16 h=__float2bfloat16(v);
        __nv_bfloat16 l=__float2bfloat16(v-__bfloat162float(h));
        uint32_t sw=SW128((uint32_t)(n*128+j*2));
        *(__nv_bfloat16*)(smc+SM_B1HI+sw)=h;
        *(__nv_bfloat16*)(smc+SM_B1LO+sw)=l;
    }
    for(int idx=t;idx<1024;idx+=256){
        int n=idx>>5,k=idx&31;
        float v=W2[k*32+n];
        __nv_bfloat16 h=__float2bfloat16(v);
        __nv_bfloat16 l=__float2bfloat16(v-__bfloat162float(h));
        *(__nv_bfloat16*)(smc+SM_W2HI+n*80+k*2)=h;
        *(__nv_bfloat16*)(smc+SM_W2LO+n*80+k*2)=l;
    }
    if(t<128) ((float*)(smc+SM_W3))[t]=W3[t];
    if(t<32){ ((float*)(smc+SM_B1V))[t]=b1[t]; ((float*)(smc+SM_B2V))[t]=b2[t]; }
    if(t<4) ((float*)(smc+SM_BOV))[t]=b3[t]+bdir[t];

    int lane=t&31, warp=t>>5;
    int g=lane>>2, i=lane&3;
    int we0=warp*16;

    for(int tile=blockIdx.x; tile<ntiles; tile+=gridDim.x){
        int e0=tile*TE;
        if(t<TE){
            int eg=e0+t; if(eg>=n_edges) eg=n_edges-1;
            int s_,d_;
            if(g_flag==0){ s_=(int)__ldg(&((const long long*)eidx)[eg]); d_=(int)__ldg(&((const long long*)eidx)[(size_t)n_edges+eg]); }
            else { s_=__ldg(&((const int*)eidx)[eg]); d_=__ldg(&((const int*)eidx)[(size_t)n_edges+eg]); }
            ((int*)(smc+SM_SRC))[t]=min(max(s_,0),n_nodes-1);
            ((int*)(smc+SM_TGT))[t]=min(max(d_,0),n_nodes-1);
        }
        __syncthreads();

        {   // gather x -> |diff| bf16 hi/lo A tiles (SW128)
            int c=t&15, el=t>>4;
            #pragma unroll
            for(int p=0;p<8;p++){
                int e=el+16*p;
                int s_=((int*)(smc+SM_SRC))[e], d_=((int*)(smc+SM_TGT))[e];
                float4 a=*(const float4*)(x+(size_t)s_*64+c*4);
                float4 b=*(const float4*)(x+(size_t)d_*64+c*4);
                float f0=fabsf(a.x-b.x),f1=fabsf(a.y-b.y),f2=fabsf(a.z-b.z),f3=fabsf(a.w-b.w);
                uint32_t h01,h23,l01,l23;
                CVT_BF16X2(h01,f0,f1); CVT_BF16X2(h23,f2,f3);
                float r0=f0-__uint_as_float(h01<<16);
                float r1=f1-__uint_as_float(h01&0xFFFF0000u);
                float r2=f2-__uint_as_float(h23<<16);
                float r3=f3-__uint_as_float(h23&0xFFFF0000u);
                CVT_BF16X2(l01,r0,r1); CVT_BF16X2(l23,r2,r3);
                uint32_t sw=SW128((uint32_t)(e*128+c*8));
                *(uint2*)(smc+SM_AHI+sw)=make_uint2(h01,h23);
                *(uint2*)(smc+SM_ALO+sw)=make_uint2(l01,l23);
            }
        }
        {   // gather P1 sums -> base (fp32 stride 36) — COALESCED
            int c=t&7, el=t>>3;
            #pragma unroll
            for(int p=0;p<4;p++){
                int e=el+32*p;
                int s_=((int*)(smc+SM_SRC))[e], d_=((int*)(smc+SM_TGT))[e];
                float4 a=*(const float4*)(g_P1+(size_t)s_*32+c*4);
                float4 b=*(const float4*)(g_P1+(size_t)d_*32+c*4);
                *(float4*)(smc+SM_BASE+(e*36+c*4)*4)=make_float4(a.x+b.x,a.y+b.y,a.z+b.z,a.w+b.w);
            }
        }
        if(t<TE){   // PD sums
            int s_=((int*)(smc+SM_SRC))[t], d_=((int*)(smc+SM_TGT))[t];
            float4 a=*(const float4*)(g_PD+(size_t)s_*4);
            float4 b=*(const float4*)(g_PD+(size_t)t!=0?(size_t)d_*4:(size_t)d_*4);
            b=*(const float4*)(g_PD+(size_t)d_*4);
            *(float4*)(smc+SM_BD+t*16)=make_float4(a.x+b.x,a.y+b.y,a.z+b.z,a.w+b.w);
        }
        __syncthreads();

        // ---- GEMM1 (hoisted frags) ----
        float acc[5][4];
        #pragma unroll
        for(int nb=0;nb<5;nb++){ acc[nb][0]=0;acc[nb][1]=0;acc[nb][2]=0;acc[nb][3]=0; }

        #pragma unroll
        for(int kb=0;kb<4;kb++){
            uint32_t ah[4],al[4];
            {
                int row=we0+(lane&15);
                uint32_t koff=((uint32_t)kb*32+((lane>>4)&1)*16)^(((uint32_t)(row&7))*16);
                ldsm4(ah,sb+SM_AHI+(uint32_t)row*128+koff);
                ldsm4(al,sb+SM_ALO+(uint32_t)row*128+koff);
            }
            #pragma unroll
            for(int nb=0;nb<5;nb++){
                int rowb=nb*8+(lane&7);
                uint32_t offb=(uint32_t)rowb*128+(((uint32_t)kb*32+((lane>>3)&1)*16)^(((uint32_t)(rowb&7))*16));
                uint32_t bh0,bh1,bl0,bl1;
                ldsm2(bh0,bh1,sb+SM_B1HI+offb);
                ldsm2(bl0,bl1,sb+SM_B1LO+offb);
                mma16816(acc[nb],ah,bh0,bh1);
                mma16816(acc[nb],ah,bl0,bl1);
                mma16816(acc[nb],al,bh0,bh1);
            }
        }

        // epilogue1: h1 = relu(acc + base + b1) cols 0..31 (in place)
        const float* baseP=(const float*)(smc+SM_BASE);
        const float* b1P=(const float*)(smc+SM_B1V);
        {
            int r0=we0+g, r8=r0+8;
            #pragma unroll
            for(int nb=0;nb<4;nb++){
                int col=nb*8+2*i;
                float2 bb=*(const float2*)(b1P+col);
                float2 q0=*(const float2*)(baseP+r0*36+col);
                float2 q8=*(const float2*)(baseP+r8*36+col);
                acc[nb][0]=fmaxf(acc[nb][0]+q0.x+bb.x,0.f);
                acc[nb][1]=fmaxf(acc[nb][1]+q0.y+bb.y,0.f);
                acc[nb][2]=fmaxf(acc[nb][2]+q8.x+bb.x,0.f);
                acc[nb][3]=fmaxf(acc[nb][3]+q8.y+bb.y,0.f);
            }
        }

        // build A2 frags (hi/lo) in registers
        uint32_t a2h[2][4], a2l[2][4];
        #pragma unroll
        for(int kb2=0;kb2<2;kb2++){
            #pragma unroll
            for(int q=0;q<4;q++){
                int nb=2*kb2+(q>>1);
                int c0=(q&1)*2;
                float v0=acc[nb][c0], v1=acc[nb][c0+1];
                uint32_t h; CVT_BF16X2(h,v0,v1);
                float r0=v0-__uint_as_float(h<<16);
                float r1=v1-__uint_as_float(h&0xFFFF0000u);
                uint32_t l; CVT_BF16X2(l,r0,r1);
                int ridx=(q>>1)*2+(q&1);
                a2h[kb2][ridx]=h; a2l[kb2][ridx]=l;
            }
        }

        // ---- GEMM2 (hoisted W frags) ----
        float acc2[4][4];
        #pragma unroll
        for(int nb=0;nb<4;nb++){ acc2[nb][0]=0;acc2[nb][1]=0;acc2[nb][2]=0;acc2[nb][3]=0; }
        #pragma unroll
        for(int kb2=0;kb2<2;kb2++){
            #pragma unroll
            for(int nb=0;nb<4;nb++){
                int rowb=nb*8+(lane&7);
                uint32_t base2=(uint32_t)rowb*80+(uint32_t)kb2*32+((lane>>3)&1)*16;
                uint32_t wh0,wh1,wl0,wl1;
                ldsm2(wh0,wh1,sb+SM_W2HI+base2);
                ldsm2(wl0,wl1,sb+SM_W2LO+base2);
                mma16816(acc2[nb],a2h[kb2],wh0,wh1);
                mma16816(acc2[nb],a2h[kb2],wl0,wl1);
                mma16816(acc2[nb],a2l[kb2],wh0,wh1);
            }
        }

        // epilogue2
        const float* b2P=(const float*)(smc+SM_B2V);
        const float* w3P=(const float*)(smc+SM_W3);
        {
            float pg[4]={0,0,0,0}, ph[4]={0,0,0,0};
            #pragma unroll
            for(int nb=0;nb<4;nb++){
                int col=nb*8+2*i;
                float2 bb=*(const float2*)(b2P+col);
                float h0=fmaxf(acc2[nb][0]+acc[nb][0]+bb.x,0.f);
                float h1v=fmaxf(acc2[nb][1]+acc[nb][1]+bb.y,0.f);
                float h2v=fmaxf(acc2[nb][2]+acc[nb][2]+bb.x,0.f);
                float h3v=fmaxf(acc2[nb][3]+acc[nb][3]+bb.y,0.f);
                float4 wa=*(const float4*)(w3P+col*4);
                float4 wb=*(const float4*)(w3P+(col+1)*4);
                pg[0]=fmaf(h0,wa.x,fmaf(h1v,wb.x,pg[0]));
                pg[1]=fmaf(h0,wa.y,fmaf(h1v,wb.y,pg[1]));
                pg[2]=fmaf(h0,wa.z,fmaf(h1v,wb.z,pg[2]));
                pg[3]=fmaf(h0,wa.w,fmaf(h1v,wb.w,pg[3]));
                ph[0]=fmaf(h2v,wa.x,fmaf(h3v,wb.x,ph[0]));
                ph[1]=fmaf(h2v,wa.y,fmaf(h3v,wb.y,ph[1]));
                ph[2]=fmaf(h2v,wa.z,fmaf(h3v,wb.z,ph[2]));
                ph[3]=fmaf(h2v,wa.w,fmaf(h3v,wb.w,ph[3]));
            }
            pg[2*i]  +=acc[4][0];
            pg[2*i+1]+=acc[4][1];
            ph[2*i]  +=acc[4][2];
            ph[2*i+1]+=acc[4][3];
            #pragma unroll
            for(int c=0;c<4;c++){
                pg[c]+=__shfl_xor_sync(0xFFFFFFFFu,pg[c],1);
                pg[c]+=__shfl_xor_sync(0xFFFFFFFFu,pg[c],2);
                ph[c]+=__shfl_xor_sync(0xFFFFFFFFu,ph[c],1);
                ph[c]+=__shfl_xor_sync(0xFFFFFFFFu,ph[c],2);
            }
            if(i==0){
                float4 bo=*(const float4*)(smc+SM_BOV);
                int el0=we0+g, el8=el0+8;
                float4 p0=*(const float4*)(smc+SM_BD+el0*16);
                float4 p8=*(const float4*)(smc+SM_BD+el8*16);
                int eg0=e0+el0, eg8=e0+el8;
                if(eg0<n_edges)
                    *(float4*)(out+(size_t)eg0*4)=make_float4(pg[0]+p0.x+bo.x,pg[1]+p0.y+bo.y,pg[2]+p0.z+bo.z,pg[3]+p0.w+bo.w);
                if(eg8<n_edges)
                    *(float4*)(out+(size_t)eg8*4)=make_float4(ph[0]+p8.x+bo.x,ph[1]+p8.y+bo.y,ph[2]+p8.z+bo.z,ph[3]+p8.w+bo.w);
            }
        }
    }
}

extern "C" void kernel_launch(void* const* d_in, const int* in_sizes, int n_in,
                              void* d_out, int out_size)
{
    const float* x=(const float*)d_in[0];
    const void* eidx=d_in[1];
    const float* Wdir=(const float*)d_in[2];
    const float* bdir=(const float*)d_in[3];
    const float* W1=(const float*)d_in[4];
    const float* b1=(const float*)d_in[5];
    const float* W2=(const float*)d_in[6];
    const float* b2=(const float*)d_in[7];
    const float* W3=(const float*)d_in[8];
    const float* b3=(const float*)d_in[9];
    float* out=(float*)d_out;

    int n_nodes=in_sizes[0]/LATENT;
    int n_edges=in_sizes[1]/2;

    int n_probe=n_edges<8192?n_edges:8192;
    probe_kernel<<<(n_probe+255)/256,256>>>((const long long*)eidx,n_probe,n_nodes);

    int npb=(n_nodes+15)/16; if(npb>1184) npb=1184;
    node_pre_kernel<<<npb,256>>>(x,W1,Wdir,n_nodes);

    cudaFuncSetAttribute(edge_kernel,cudaFuncAttributeMaxDynamicSharedMemorySize,SM_TOTAL);
    int ntiles=(n_edges+TE-1)/TE;
    int nblk=444; if(ntiles<nblk) nblk=ntiles;
    edge_kernel<<<nblk,256,SM_TOTAL>>>(x,eidx,Wdir,bdir,W1,b1,W2,b2,W3,b3,out,n_edges,n_nodes,ntiles);
}